// round 8
// baseline (speedup 1.0000x reference)
#include <cuda_runtime.h>
#include <math.h>

typedef unsigned long long u64;

#define BB   32
#define CC   128
#define ICC  256
#define HWD  4096
#define HIDD 512

// ---------------- scratch (static __device__, no allocation) ----------------
__device__ float g_kpT[CC * ICC];              // k' transposed: [c][o]
__device__ float g_kb[ICC];                    // BN1 bias folded through k
__device__ float g_inv2[CC], g_beta2[CC];      // BN2 folded params
__device__ float g_rowmax[BB * ICC], g_rowsum[BB * ICC];
__device__ float g_h[(size_t)BB * ICC * HWD];  // 128 MiB attention map
__device__ float g_xr[(size_t)BB * CC * HWD];  // 64 MiB residual x + attn
__device__ float g_t[(size_t)BB * HIDD * HWD]; // 256 MiB hidden activations

// ---------------- f32x2 helpers (FFMA2: 2x FP32 rate on sm_103a) ------------
__device__ __forceinline__ u64 splat2(float v) {
    u64 r; unsigned int u = __float_as_uint(v);
    asm("mov.b64 %0, {%1, %1};" : "=l"(r) : "r"(u));
    return r;
}
__device__ __forceinline__ void fma2(u64& d, u64 a, u64 b) {
    asm("fma.rn.f32x2 %0, %1, %2, %0;" : "+l"(d) : "l"(a), "l"(b));
}
__device__ __forceinline__ void unpack2(u64 p, float& lo, float& hi) {
    unsigned int l, h;
    asm("mov.b64 {%0, %1}, %2;" : "=r"(l), "=r"(h) : "l"(p));
    lo = __uint_as_float(l); hi = __uint_as_float(h);
}

// ---------------- K0: fold BN1 into k, precompute BN2 params ----------------
__global__ void k_fold(const float* __restrict__ bn1_g, const float* __restrict__ bn1_b,
                       const float* __restrict__ bn1_m, const float* __restrict__ bn1_v,
                       const float* __restrict__ kmat,
                       const float* __restrict__ bn2_g, const float* __restrict__ bn2_b,
                       const float* __restrict__ bn2_m, const float* __restrict__ bn2_v) {
    __shared__ float inv1[CC], beta1[CC];
    int t = threadIdx.x;
    if (t < CC) {
        float iv = bn1_g[t] * rsqrtf(bn1_v[t] + 1e-5f);
        inv1[t] = iv;
        beta1[t] = bn1_b[t] - bn1_m[t] * iv;
        float iv2 = bn2_g[t] * rsqrtf(bn2_v[t] + 1e-6f);
        g_inv2[t] = iv2;
        g_beta2[t] = bn2_b[t] - bn2_m[t] * iv2;
    }
    __syncthreads();
    int o = t;  // 0..255
    float s = 0.f;
    for (int c = 0; c < CC; ++c) {
        float kv = kmat[o * CC + c];
        g_kpT[c * ICC + o] = kv * inv1[c];
        s += kv * beta1[c];
    }
    g_kb[o] = s;
}

// ------- K1: h[b,o,s] = kb[o] + sum_c k'[o,c] x[b,c,s]  (f32x2 inner) -------
__global__ void k_gemm1(const float* __restrict__ x) {
    int b = blockIdx.z, o0 = blockIdx.y * 64, s0 = blockIdx.x * 128;
    int tid = threadIdx.x, ty = tid >> 4, tx = tid & 15;
    __shared__ __align__(16) float As[32][64];    // [kk][o_local]
    __shared__ __align__(16) float Bs[32][128];   // [kk][s_local]
    u64 acc[4][4];   // [oc i][spatial pair p] ; 0ull == {+0.f,+0.f}
#pragma unroll
    for (int i = 0; i < 4; ++i)
#pragma unroll
        for (int p = 0; p < 4; ++p) acc[i][p] = 0ULL;
    const float* xb = x + (size_t)b * CC * HWD + s0;
    for (int kc = 0; kc < 4; ++kc) {
        for (int g = tid; g < 2048; g += 256) {
            int kk = g >> 6, ol = g & 63;
            As[kk][ol] = g_kpT[(kc * 32 + kk) * ICC + o0 + ol];
        }
        for (int g = tid; g < 4096; g += 256) {
            int kk = g >> 7, ss = g & 127;
            Bs[kk][ss] = xb[(size_t)(kc * 32 + kk) * HWD + ss];
        }
        __syncthreads();
#pragma unroll 8
        for (int kk = 0; kk < 32; ++kk) {
            float4 av = *(const float4*)&As[kk][ty * 4];
            u64 a0 = splat2(av.x), a1 = splat2(av.y);
            u64 a2 = splat2(av.z), a3 = splat2(av.w);
            u64 bp[4];
#pragma unroll
            for (int p = 0; p < 4; ++p)
                bp[p] = *(const u64*)&Bs[kk][tx * 8 + 2 * p];
#pragma unroll
            for (int p = 0; p < 4; ++p) {
                fma2(acc[0][p], a0, bp[p]);
                fma2(acc[1][p], a1, bp[p]);
                fma2(acc[2][p], a2, bp[p]);
                fma2(acc[3][p], a3, bp[p]);
            }
        }
        __syncthreads();
    }
#pragma unroll
    for (int i = 0; i < 4; ++i) {
        int o = o0 + ty * 4 + i;
        float kb = g_kb[o];
        float r[8];
#pragma unroll
        for (int p = 0; p < 4; ++p) {
            float lo, hi; unpack2(acc[i][p], lo, hi);
            r[2 * p] = lo + kb; r[2 * p + 1] = hi + kb;
        }
        float* hp = &g_h[((size_t)b * ICC + o) * HWD + s0 + tx * 8];
        *(float4*)hp = make_float4(r[0], r[1], r[2], r[3]);
        *(float4*)(hp + 4) = make_float4(r[4], r[5], r[6], r[7]);
    }
}

// ---------------- K2: per-row (b,o) max & sum of exp over 4096 spatial ------
__global__ void k_rowstats() {
    int r = blockIdx.x;
    const float4* p = (const float4*)(g_h + (size_t)r * HWD);
    int t = threadIdx.x;
    float v[16];
#pragma unroll
    for (int k = 0; k < 4; ++k) {
        float4 f = p[t + k * 256];
        v[k * 4 + 0] = f.x; v[k * 4 + 1] = f.y; v[k * 4 + 2] = f.z; v[k * 4 + 3] = f.w;
    }
    float m = v[0];
#pragma unroll
    for (int i = 1; i < 16; ++i) m = fmaxf(m, v[i]);
    __shared__ float red[256];
    red[t] = m; __syncthreads();
    for (int off = 128; off > 0; off >>= 1) {
        if (t < off) red[t] = fmaxf(red[t], red[t + off]);
        __syncthreads();
    }
    float rmax = red[0];
    __syncthreads();
    float s = 0.f;
#pragma unroll
    for (int i = 0; i < 16; ++i) s += __expf(v[i] - rmax);
    red[t] = s; __syncthreads();
    for (int off = 128; off > 0; off >>= 1) {
        if (t < off) red[t] += red[t + off];
        __syncthreads();
    }
    if (t == 0) { g_rowmax[r] = rmax; g_rowsum[r] = red[0]; }
}

// -------- K3: softmax over spatial + per-head channel-sum normalization -----
__global__ void k_dnorm() {
    int s = blockIdx.x * 256 + threadIdx.x;
    int nh = blockIdx.y, b = blockIdx.z;
    __shared__ float smax[32], sinv[32];
    if (threadIdx.x < 32) {
        int rr = b * ICC + nh * 32 + threadIdx.x;
        smax[threadIdx.x] = g_rowmax[rr];
        sinv[threadIdx.x] = 1.0f / g_rowsum[rr];
    }
    __syncthreads();
    float e[32];
    float d = 0.f;
    float* base = g_h + ((size_t)b * ICC + nh * 32) * HWD + s;
#pragma unroll
    for (int c = 0; c < 32; ++c) {
        float val = __expf(base[(size_t)c * HWD] - smax[c]) * sinv[c];
        e[c] = val; d += val;
    }
    float w = 1.0f / (d + 1e-6f);
#pragma unroll
    for (int c = 0; c < 32; ++c) base[(size_t)c * HWD] = e[c] * w;
}

// -------- K4: xr = x + v@h2   (f32x2 inner; BN2 moved into conv1 staging) ---
__global__ void k_gemm2(const float* __restrict__ x, const float* __restrict__ vmat) {
    int b = blockIdx.z, c0 = blockIdx.y * 64, s0 = blockIdx.x * 128;
    int tid = threadIdx.x, ty = tid >> 4, tx = tid & 15;
    __shared__ __align__(16) float As[32][65];   // [kk][c_local], padded
    __shared__ __align__(16) float Bs[32][128];
    u64 acc[4][4];
#pragma unroll
    for (int i = 0; i < 4; ++i)
#pragma unroll
        for (int p = 0; p < 4; ++p) acc[i][p] = 0ULL;
    const float* hb = g_h + (size_t)b * ICC * HWD + s0;
    for (int kc = 0; kc < 8; ++kc) {
        for (int g = tid; g < 2048; g += 256) {
            int cl = g >> 5, kk = g & 31;
            As[kk][cl] = vmat[(c0 + cl) * ICC + kc * 32 + kk];
        }
        for (int g = tid; g < 4096; g += 256) {
            int kk = g >> 7, ss = g & 127;
            Bs[kk][ss] = hb[(size_t)(kc * 32 + kk) * HWD + ss];
        }
        __syncthreads();
#pragma unroll 8
        for (int kk = 0; kk < 32; ++kk) {
            u64 a0 = splat2(As[kk][ty * 4 + 0]);
            u64 a1 = splat2(As[kk][ty * 4 + 1]);
            u64 a2 = splat2(As[kk][ty * 4 + 2]);
            u64 a3 = splat2(As[kk][ty * 4 + 3]);
            u64 bp[4];
#pragma unroll
            for (int p = 0; p < 4; ++p)
                bp[p] = *(const u64*)&Bs[kk][tx * 8 + 2 * p];
#pragma unroll
            for (int p = 0; p < 4; ++p) {
                fma2(acc[0][p], a0, bp[p]);
                fma2(acc[1][p], a1, bp[p]);
                fma2(acc[2][p], a2, bp[p]);
                fma2(acc[3][p], a3, bp[p]);
            }
        }
        __syncthreads();
    }
#pragma unroll
    for (int i = 0; i < 4; ++i) {
        int c = c0 + ty * 4 + i;
        size_t idx = ((size_t)b * CC + c) * HWD + s0 + tx * 8;
        float4 x0v = *(const float4*)(x + idx);
        float4 x1v = *(const float4*)(x + idx + 4);
        float r[8];
#pragma unroll
        for (int p = 0; p < 4; ++p) {
            float lo, hi; unpack2(acc[i][p], lo, hi);
            r[2 * p] = lo; r[2 * p + 1] = hi;
        }
        *(float4*)(g_xr + idx) = make_float4(x0v.x + r[0], x0v.y + r[1],
                                             x0v.z + r[2], x0v.w + r[3]);
        *(float4*)(g_xr + idx + 4) = make_float4(x1v.x + r[4], x1v.y + r[5],
                                                 x1v.z + r[6], x1v.w + r[7]);
    }
}

// ---------------- 3x3 SAME conv, f32x2 dual-rate FMA ------------------------
// Block: one image row (y) x 64 output channels for one batch image.
// 128 threads: thread = 4 oc (2 f32x2 pairs) x 8 x positions.
// MODE 0: in=g_xr (BN2 applied during staging) -> bias + exact GELU -> g_t
// MODE 1: in=g_t  -> bias + g_xr residual -> d_out
#define CONV_CK    16
#define CONV_INROW 68
#define CONV_WROW  66
#define CONV_SMEM  ((CONV_CK * 3 * CONV_INROW + CONV_CK * 9 * CONV_WROW) * 4)

template <int MODE>
__global__ void __launch_bounds__(128) k_conv3x3(const float* __restrict__ w,
                                                 const float* __restrict__ bias,
                                                 float* __restrict__ dout) {
    constexpr int ICT = (MODE == 0) ? 128 : 512;
    const float* in = (MODE == 0) ? g_xr : g_t;

    extern __shared__ float sm[];
    float* In = sm;                             // [CK][3][68], col 0 => x=-1
    float* Ws = sm + CONV_CK * 3 * CONV_INROW;  // [kk*9+tap][66] (oc along row)
    __shared__ float s_inv2[CC], s_beta2[CC];   // MODE0 only

    int y = blockIdx.x;
    int oc0 = blockIdx.y * 64;
    int b = blockIdx.z;
    int tid = threadIdx.x;
    int tx = tid & 7, ty = tid >> 3;
    int x0 = tx * 8;

    if (MODE == 0) {
        if (tid < CC) { s_inv2[tid] = g_inv2[tid]; s_beta2[tid] = g_beta2[tid]; }
    }
    __syncthreads();

    u64 acc01[8], acc23[8];
#pragma unroll
    for (int j = 0; j < 8; ++j) { acc01[j] = 0ULL; acc23[j] = 0ULL; }

    const float* inb = in + (size_t)b * ICT * HWD;
    const float* wb = w + (size_t)oc0 * ICT * 9;

    for (int cbase = 0; cbase < ICT; cbase += CONV_CK) {
        // stage input tile: rows y-1..y+1, x = -1..66 (zero-padded borders)
        for (int g = tid; g < CONV_CK * 3 * CONV_INROW; g += 128) {
            int kk = g / (3 * CONV_INROW);
            int rem = g - kk * (3 * CONV_INROW);
            int dy = rem / CONV_INROW;
            int col = rem - dy * CONV_INROW;
            int xx = col - 1;
            int yy = y + dy - 1;
            float val = 0.f;
            if ((unsigned)xx < 64u && (unsigned)yy < 64u) {
                val = inb[(size_t)(cbase + kk) * HWD + yy * 64 + xx];
                if (MODE == 0)
                    val = val * s_inv2[cbase + kk] + s_beta2[cbase + kk];
            }
            In[(kk * 3 + dy) * CONV_INROW + col] = val;
        }
        // stage weights: [oc][(cbase+kk)*9+tap] -> smem [kk*9+tap][oc]
        for (int g = tid; g < 64 * CONV_CK * 9; g += 128) {
            int oc = g / (CONV_CK * 9);
            int rr = g - oc * (CONV_CK * 9);
            Ws[rr * CONV_WROW + oc] = wb[(size_t)oc * (ICT * 9) + cbase * 9 + rr];
        }
        __syncthreads();
#pragma unroll 2
        for (int kk = 0; kk < CONV_CK; ++kk) {
#pragma unroll
            for (int dy = 0; dy < 3; ++dy) {
                const float* ip = In + (kk * 3 + dy) * CONV_INROW + x0;
                float4 f0 = *(const float4*)ip;
                float4 f1 = *(const float4*)(ip + 4);
                float2 f2 = *(const float2*)(ip + 8);
                u64 irp[10];
                irp[0] = splat2(f0.x); irp[1] = splat2(f0.y);
                irp[2] = splat2(f0.z); irp[3] = splat2(f0.w);
                irp[4] = splat2(f1.x); irp[5] = splat2(f1.y);
                irp[6] = splat2(f1.z); irp[7] = splat2(f1.w);
                irp[8] = splat2(f2.x); irp[9] = splat2(f2.y);
#pragma unroll
                for (int dx = 0; dx < 3; ++dx) {
                    int rr = kk * 9 + dy * 3 + dx;
                    u64 w01 = *(const u64*)(Ws + rr * CONV_WROW + ty * 4);
                    u64 w23 = *(const u64*)(Ws + rr * CONV_WROW + ty * 4 + 2);
#pragma unroll
                    for (int j = 0; j < 8; ++j) {
                        fma2(acc01[j], w01, irp[j + dx]);
                        fma2(acc23[j], w23, irp[j + dx]);
                    }
                }
            }
        }
        __syncthreads();
    }

    float a[4][8];
#pragma unroll
    for (int j = 0; j < 8; ++j) {
        unpack2(acc01[j], a[0][j], a[1][j]);
        unpack2(acc23[j], a[2][j], a[3][j]);
    }

    if (MODE == 0) {
#pragma unroll
        for (int i = 0; i < 4; ++i) {
            int oc = oc0 + ty * 4 + i;
            float bb = bias[oc];
            float* op = g_t + ((size_t)b * HIDD + oc) * HWD + y * 64 + x0;
#pragma unroll
            for (int j = 0; j < 8; ++j) {
                float t = a[i][j] + bb;
                op[j] = 0.5f * t * (1.0f + erff(t * 0.70710678118654752f));
            }
        }
    } else {
#pragma unroll
        for (int i = 0; i < 4; ++i) {
            int oc = oc0 + ty * 4 + i;
            float bb = bias[oc];
            size_t idx = ((size_t)b * CC + oc) * HWD + y * 64 + x0;
            const float* xrp = g_xr + idx;
#pragma unroll
            for (int j = 0; j < 8; ++j) dout[idx + j] = a[i][j] + bb + xrp[j];
        }
    }
}

// ---------------------------------------------------------------------------
extern "C" void kernel_launch(void* const* d_in, const int* in_sizes, int n_in,
                              void* d_out, int out_size) {
    (void)in_sizes; (void)n_in; (void)out_size;
    const float* x     = (const float*)d_in[0];
    const float* bn1_g = (const float*)d_in[1];
    const float* bn1_b = (const float*)d_in[2];
    const float* bn1_m = (const float*)d_in[3];
    const float* bn1_v = (const float*)d_in[4];
    const float* kmat  = (const float*)d_in[5];
    const float* vmat  = (const float*)d_in[6];
    const float* bn2_g = (const float*)d_in[7];
    const float* bn2_b = (const float*)d_in[8];
    const float* bn2_m = (const float*)d_in[9];
    const float* bn2_v = (const float*)d_in[10];
    const float* w1    = (const float*)d_in[11];
    const float* b1    = (const float*)d_in[12];
    const float* w2    = (const float*)d_in[13];
    const float* b2    = (const float*)d_in[14];
    float* out = (float*)d_out;

    static bool attr_done = false;
    if (!attr_done) {
        cudaFuncSetAttribute(k_conv3x3<0>, cudaFuncAttributeMaxDynamicSharedMemorySize, CONV_SMEM);
        cudaFuncSetAttribute(k_conv3x3<1>, cudaFuncAttributeMaxDynamicSharedMemorySize, CONV_SMEM);
        attr_done = true;
    }

    k_fold<<<1, 256>>>(bn1_g, bn1_b, bn1_m, bn1_v, kmat,
                       bn2_g, bn2_b, bn2_m, bn2_v);

    dim3 g1(HWD / 128, ICC / 64, BB);
    k_gemm1<<<g1, 256>>>(x);

    k_rowstats<<<BB * ICC, 256>>>();

    dim3 gd(HWD / 256, 8, BB);
    k_dnorm<<<gd, 256>>>();

    dim3 g2(HWD / 128, CC / 64, BB);
    k_gemm2<<<g2, 256>>>(x, vmat);

    dim3 gc1(64, HIDD / 64, BB);
    k_conv3x3<0><<<gc1, 128, CONV_SMEM>>>(w1, b1, nullptr);

    dim3 gc2(64, CC / 64, BB);
    k_conv3x3<1><<<gc2, 128, CONV_SMEM>>>(w2, b2, out);
}

// round 9
// speedup vs baseline: 1.5293x; 1.5293x over previous
#include <cuda_runtime.h>
#include <math.h>

typedef unsigned long long u64;
typedef unsigned int u32;
typedef unsigned short u16;

#define BB   32
#define CC   128
#define ICC  256
#define HWD  4096
#define HIDD 512

// ---------------- scratch (static __device__, no allocation) ----------------
__device__ float g_kb[ICC];                    // BN1 bias folded through k
__device__ float g_inv2[CC], g_beta2[CC];      // BN2 folded params
__device__ float g_rowmax[BB * ICC], g_rowsum[BB * ICC];
__device__ float g_h[(size_t)BB * ICC * HWD];  // 128 MiB attention map
__device__ float g_xr[(size_t)BB * CC * HWD];  // 64 MiB residual x + attn
__device__ float g_t[(size_t)BB * HIDD * HWD]; // 256 MiB hidden activations

// bf16 hi/lo split weight banks (natural [oc][k] layouts)
__device__ u16 g_kA_h[ICC * CC],      g_kA_l[ICC * CC];       // k' [256][128]
__device__ u16 g_vA_h[CC * ICC],      g_vA_l[CC * ICC];       // v  [128][256]
__device__ u16 g_w1h[HIDD * CC * 9],  g_w1l[HIDD * CC * 9];   // w1 [512][1152]
__device__ u16 g_w2h[CC * HIDD * 9],  g_w2l[CC * HIDD * 9];   // w2 [128][4608]

// ---------------- helpers ----------------------------------------------------
__device__ __forceinline__ u16 bf16_rn(float v, float& hf) {
    u32 u = __float_as_uint(v);
    u32 r = (u + 0x7FFFu + ((u >> 16) & 1u)) & 0xFFFF0000u;
    hf = __uint_as_float(r);
    return (u16)(r >> 16);
}
__device__ __forceinline__ void split_bf16(float v, u16& h, u16& l) {
    float hf; h = bf16_rn(v, hf);
    float d; l = bf16_rn(v - hf, d);
}
__device__ __forceinline__ void mma16816(float& c0, float& c1, float& c2, float& c3,
                                         u32 a0, u32 a1, u32 a2, u32 a3,
                                         u32 b0, u32 b1) {
    asm volatile(
        "mma.sync.aligned.m16n8k16.row.col.f32.bf16.bf16.f32 "
        "{%0,%1,%2,%3},{%4,%5,%6,%7},{%8,%9},{%0,%1,%2,%3};"
        : "+f"(c0), "+f"(c1), "+f"(c2), "+f"(c3)
        : "r"(a0), "r"(a1), "r"(a2), "r"(a3), "r"(b0), "r"(b1));
}
__device__ __forceinline__ float gelu_exact(float v) {
    return 0.5f * v * (1.0f + erff(v * 0.70710678118654752f));
}

// ---------------- K0: fold BN1 into k (split bf16), BN2 params --------------
__global__ void k_fold(const float* __restrict__ bn1_g, const float* __restrict__ bn1_b,
                       const float* __restrict__ bn1_m, const float* __restrict__ bn1_v,
                       const float* __restrict__ kmat,
                       const float* __restrict__ bn2_g, const float* __restrict__ bn2_b,
                       const float* __restrict__ bn2_m, const float* __restrict__ bn2_v) {
    __shared__ float inv1[CC], beta1[CC];
    int t = threadIdx.x;
    if (t < CC) {
        float iv = bn1_g[t] * rsqrtf(bn1_v[t] + 1e-5f);
        inv1[t] = iv;
        beta1[t] = bn1_b[t] - bn1_m[t] * iv;
        float iv2 = bn2_g[t] * rsqrtf(bn2_v[t] + 1e-6f);
        g_inv2[t] = iv2;
        g_beta2[t] = bn2_b[t] - bn2_m[t] * iv2;
    }
    __syncthreads();
    int o = t;  // 0..255
    float s = 0.f;
    for (int c = 0; c < CC; ++c) {
        float kv = kmat[o * CC + c];
        u16 h, l; split_bf16(kv * inv1[c], h, l);
        g_kA_h[o * CC + c] = h;
        g_kA_l[o * CC + c] = l;
        s += kv * beta1[c];
    }
    g_kb[o] = s;
}

// ---------------- K0b: split conv weights + v bank into bf16 hi/lo ----------
__global__ void k_prep_w(const float* __restrict__ w1, const float* __restrict__ w2,
                         const float* __restrict__ vmat) {
    const int n1 = HIDD * CC * 9;    // 589824
    const int n2 = CC * HIDD * 9;    // 589824
    const int n3 = CC * ICC;         // 32768
    int stride = gridDim.x * blockDim.x;
    for (int i = blockIdx.x * blockDim.x + threadIdx.x; i < n1 + n2 + n3; i += stride) {
        u16 h, l;
        if (i < n1) {
            split_bf16(w1[i], h, l);
            g_w1h[i] = h; g_w1l[i] = l;
        } else if (i < n1 + n2) {
            int j = i - n1;
            split_bf16(w2[j], h, l);
            g_w2h[j] = h; g_w2l[j] = l;
        } else {
            int j = i - n1 - n2;
            split_bf16(vmat[j], h, l);
            g_vA_h[j] = h; g_vA_l[j] = l;
        }
    }
}

// ---------------- 1x1 GEMMs via mma (split-bf16, 3 MMAs per tile) -----------
// MODE 0: g_h[b,o,s] = kb[o] + sum_c k'[o,c] * x[b,c,s]      (M=256, K=128)
// MODE 1: g_xr[b,c,s] = x[b,c,s] + sum_ic v[c,ic]*g_h[b,ic,s] (M=128, K=256)
template <int MODE>
__global__ void __launch_bounds__(256) k_gemm_mma(const float* __restrict__ x) {
    constexpr int K  = (MODE == 0) ? CC : ICC;
    constexpr int KW = K / 2 + 4;            // padded words per B row (68 / 132)
    extern __shared__ float sm[];
    float* In = sm;                          // [64][65] raw fp32 chunk
    u32* Bh = (u32*)(sm + 64 * 65);          // [64][KW]
    u32* Bl = Bh + 64 * KW;

    const u16* Ah = (MODE == 0) ? g_kA_h : g_vA_h;
    const u16* Al = (MODE == 0) ? g_kA_l : g_vA_l;
    const float* src = (MODE == 0) ? x : g_h;

    int s0 = blockIdx.x * 64, oc0 = blockIdx.y * 128, b = blockIdx.z;
    int tid = threadIdx.x;
    int w = tid >> 5, lane = tid & 31;
    int g = lane >> 2, t = lane & 3;

    float acc[8][4];
#pragma unroll
    for (int nt = 0; nt < 8; ++nt)
#pragma unroll
        for (int q = 0; q < 4; ++q) acc[nt][q] = 0.f;

    // build B (all K), chunked by 64 channels
    for (int ch = 0; ch < K / 64; ++ch) {
        for (int i = tid; i < 4096; i += 256) {
            int kl = i >> 6, n = i & 63;
            In[kl * 65 + n] = src[((size_t)b * K + ch * 64 + kl) * HWD + s0 + n];
        }
        __syncthreads();
        for (int i = tid; i < 2048; i += 256) {
            int kp = i & 31, n = i >> 5;
            float v0 = In[(2 * kp) * 65 + n];
            float v1 = In[(2 * kp + 1) * 65 + n];
            u16 h0, l0, h1, l1;
            split_bf16(v0, h0, l0);
            split_bf16(v1, h1, l1);
            Bh[n * KW + ch * 32 + kp] = (u32)h0 | ((u32)h1 << 16);
            Bl[n * KW + ch * 32 + kp] = (u32)l0 | ((u32)l1 << 16);
        }
        __syncthreads();
    }

    int rowA = oc0 + w * 16 + g;
    const u16* pAh = Ah + (size_t)rowA * K;
    const u16* pAl = Al + (size_t)rowA * K;

    for (int ks = 0; ks < K / 16; ++ks) {
        int kc = ks * 16 + t * 2;
        u32 ah0 = *(const u32*)(pAh + kc);
        u32 ah1 = *(const u32*)(pAh + (size_t)8 * K + kc);
        u32 ah2 = *(const u32*)(pAh + kc + 8);
        u32 ah3 = *(const u32*)(pAh + (size_t)8 * K + kc + 8);
        u32 al0 = *(const u32*)(pAl + kc);
        u32 al1 = *(const u32*)(pAl + (size_t)8 * K + kc);
        u32 al2 = *(const u32*)(pAl + kc + 8);
        u32 al3 = *(const u32*)(pAl + (size_t)8 * K + kc + 8);
        int kw = ks * 8 + t;
#pragma unroll
        for (int nt = 0; nt < 8; ++nt) {
            const u32* pb = Bh + (nt * 8 + g) * KW + kw;
            const u32* pl = Bl + (nt * 8 + g) * KW + kw;
            u32 bh0 = pb[0], bh1 = pb[4];
            u32 bl0 = pl[0], bl1 = pl[4];
            mma16816(acc[nt][0], acc[nt][1], acc[nt][2], acc[nt][3],
                     ah0, ah1, ah2, ah3, bh0, bh1);
            mma16816(acc[nt][0], acc[nt][1], acc[nt][2], acc[nt][3],
                     ah0, ah1, ah2, ah3, bl0, bl1);
            mma16816(acc[nt][0], acc[nt][1], acc[nt][2], acc[nt][3],
                     al0, al1, al2, al3, bh0, bh1);
        }
    }

    // epilogue
#pragma unroll
    for (int nt = 0; nt < 8; ++nt) {
        int px = s0 + nt * 8 + t * 2;
        int r0 = rowA, r1 = rowA + 8;
        if (MODE == 0) {
            float k0 = g_kb[r0], k1 = g_kb[r1];
            size_t i0 = ((size_t)b * ICC + r0) * HWD + px;
            size_t i1 = ((size_t)b * ICC + r1) * HWD + px;
            *(float2*)(g_h + i0) = make_float2(acc[nt][0] + k0, acc[nt][1] + k0);
            *(float2*)(g_h + i1) = make_float2(acc[nt][2] + k1, acc[nt][3] + k1);
        } else {
            size_t i0 = ((size_t)b * CC + r0) * HWD + px;
            size_t i1 = ((size_t)b * CC + r1) * HWD + px;
            float2 x0 = *(const float2*)(x + i0);
            float2 x1 = *(const float2*)(x + i1);
            *(float2*)(g_xr + i0) = make_float2(acc[nt][0] + x0.x, acc[nt][1] + x0.y);
            *(float2*)(g_xr + i1) = make_float2(acc[nt][2] + x1.x, acc[nt][3] + x1.y);
        }
    }
}

// ---------------- K2: per-row (b,o) max & sum of exp over 4096 spatial ------
__global__ void k_rowstats() {
    int r = blockIdx.x;
    const float4* p = (const float4*)(g_h + (size_t)r * HWD);
    int t = threadIdx.x;
    float v[16];
#pragma unroll
    for (int k = 0; k < 4; ++k) {
        float4 f = p[t + k * 256];
        v[k * 4 + 0] = f.x; v[k * 4 + 1] = f.y; v[k * 4 + 2] = f.z; v[k * 4 + 3] = f.w;
    }
    float m = v[0];
#pragma unroll
    for (int i = 1; i < 16; ++i) m = fmaxf(m, v[i]);
    __shared__ float red[256];
    red[t] = m; __syncthreads();
    for (int off = 128; off > 0; off >>= 1) {
        if (t < off) red[t] = fmaxf(red[t], red[t + off]);
        __syncthreads();
    }
    float rmax = red[0];
    __syncthreads();
    float s = 0.f;
#pragma unroll
    for (int i = 0; i < 16; ++i) s += __expf(v[i] - rmax);
    red[t] = s; __syncthreads();
    for (int off = 128; off > 0; off >>= 1) {
        if (t < off) red[t] += red[t + off];
        __syncthreads();
    }
    if (t == 0) { g_rowmax[r] = rmax; g_rowsum[r] = red[0]; }
}

// -------- K3: softmax over spatial + per-head channel-sum normalization -----
__global__ void k_dnorm() {
    int s = blockIdx.x * 256 + threadIdx.x;
    int nh = blockIdx.y, b = blockIdx.z;
    __shared__ float smax[32], sinv[32];
    if (threadIdx.x < 32) {
        int rr = b * ICC + nh * 32 + threadIdx.x;
        smax[threadIdx.x] = g_rowmax[rr];
        sinv[threadIdx.x] = 1.0f / g_rowsum[rr];
    }
    __syncthreads();
    float e[32];
    float d = 0.f;
    float* base = g_h + ((size_t)b * ICC + nh * 32) * HWD + s;
#pragma unroll
    for (int c = 0; c < 32; ++c) {
        float val = __expf(base[(size_t)c * HWD] - smax[c]) * sinv[c];
        e[c] = val; d += val;
    }
    float w = 1.0f / (d + 1e-6f);
#pragma unroll
    for (int c = 0; c < 32; ++c) base[(size_t)c * HWD] = e[c] * w;
}

// ---------------- 3x3 conv as implicit GEMM on tensor cores -----------------
// Block: one (b, y, 128-oc group). M=oc(128 per block), N=64 px, K=ic*9.
// MODE 0: in = g_xr (BN2 in staging) -> bias + exact GELU -> g_t   (128->512)
// MODE 1: in = g_t  -> bias + g_xr residual -> dout                (512->128)
#define CBKW 76   // padded B row in words (152 bf16)
#define CONV_SMEM ((3168 + 2 * 64 * CBKW) * 4)

template <int MODE>
__global__ void __launch_bounds__(256) k_conv_mma(const float* __restrict__ bias,
                                                  float* __restrict__ dout) {
    constexpr int ICT = (MODE == 0) ? 128 : 512;
    constexpr int Kt  = ICT * 9;
    const float* in = (MODE == 0) ? g_xr : g_t;
    const u16* Wh = (MODE == 0) ? g_w1h : g_w2h;
    const u16* Wl = (MODE == 0) ? g_w1l : g_w2l;

    extern __shared__ float sm[];
    float* In = sm;                          // [16][3][66] fp32, col0 => x=-1
    u32* Bh = (u32*)(sm + 3168);             // [64][76] packed bf16 pairs
    u32* Bl = Bh + 64 * CBKW;

    int y = blockIdx.x, oc0 = blockIdx.y * 128, b = blockIdx.z;
    int tid = threadIdx.x;
    int w = tid >> 5, lane = tid & 31;
    int g = lane >> 2, t = lane & 3;

    float acc[8][4];
#pragma unroll
    for (int nt = 0; nt < 8; ++nt)
#pragma unroll
        for (int q = 0; q < 4; ++q) acc[nt][q] = 0.f;

    const float* inb = in + (size_t)b * ICT * HWD;
    int rowA = oc0 + w * 16 + g;
    const u16* pWh = Wh + (size_t)rowA * Kt;
    const u16* pWl = Wl + (size_t)rowA * Kt;

    for (int ch = 0; ch < ICT / 16; ++ch) {
        // phase1: raw input slab rows y-1..y+1, x=-1..64, 16 channels
        for (int i = tid; i < 3168; i += 256) {
            int ic = i / 198, r = i - ic * 198;
            int dy = r / 66, col = r - dy * 66;
            int xx = col - 1, yy = y + dy - 1;
            float val = 0.f;
            if ((unsigned)xx < 64u && (unsigned)yy < 64u) {
                val = inb[(size_t)(ch * 16 + ic) * HWD + yy * 64 + xx];
                if (MODE == 0)
                    val = val * g_inv2[ch * 16 + ic] + g_beta2[ch * 16 + ic];
            }
            In[(ic * 3 + dy) * 66 + col] = val;
        }
        __syncthreads();
        // phase2: im2col into split-bf16 B [n][k], k = ic*9 + dy*3 + dx
        for (int i = tid; i < 4608; i += 256) {
            int kp = i % 72, n = i / 72;
            int k0 = kp * 2, k1 = k0 + 1;
            int ic0 = k0 / 9, tp0 = k0 - ic0 * 9;
            int ic1 = k1 / 9, tp1 = k1 - ic1 * 9;
            float v0 = In[(ic0 * 3 + tp0 / 3) * 66 + n + (tp0 % 3)];
            float v1 = In[(ic1 * 3 + tp1 / 3) * 66 + n + (tp1 % 3)];
            u16 h0, l0, h1, l1;
            split_bf16(v0, h0, l0);
            split_bf16(v1, h1, l1);
            Bh[n * CBKW + kp] = (u32)h0 | ((u32)h1 << 16);
            Bl[n * CBKW + kp] = (u32)l0 | ((u32)l1 << 16);
        }
        __syncthreads();
        // mma over this chunk's 144 k values (9 k-steps of 16)
        int kg0 = ch * 144;
        for (int ks = 0; ks < 9; ++ks) {
            int kc = kg0 + ks * 16 + t * 2;
            u32 ah0 = *(const u32*)(pWh + kc);
            u32 ah1 = *(const u32*)(pWh + (size_t)8 * Kt + kc);
            u32 ah2 = *(const u32*)(pWh + kc + 8);
            u32 ah3 = *(const u32*)(pWh + (size_t)8 * Kt + kc + 8);
            u32 al0 = *(const u32*)(pWl + kc);
            u32 al1 = *(const u32*)(pWl + (size_t)8 * Kt + kc);
            u32 al2 = *(const u32*)(pWl + kc + 8);
            u32 al3 = *(const u32*)(pWl + (size_t)8 * Kt + kc + 8);
            int kw = ks * 8 + t;
#pragma unroll
            for (int nt = 0; nt < 8; ++nt) {
                const u32* pb = Bh + (nt * 8 + g) * CBKW + kw;
                const u32* pl = Bl + (nt * 8 + g) * CBKW + kw;
                u32 bh0 = pb[0], bh1 = pb[4];
                u32 bl0 = pl[0], bl1 = pl[4];
                mma16816(acc[nt][0], acc[nt][1], acc[nt][2], acc[nt][3],
                         ah0, ah1, ah2, ah3, bh0, bh1);
                mma16816(acc[nt][0], acc[nt][1], acc[nt][2], acc[nt][3],
                         ah0, ah1, ah2, ah3, bl0, bl1);
                mma16816(acc[nt][0], acc[nt][1], acc[nt][2], acc[nt][3],
                         al0, al1, al2, al3, bh0, bh1);
            }
        }
        __syncthreads();
    }

    // epilogue
    int r0 = rowA, r1 = rowA + 8;
    float b0v = bias[r0], b1v = bias[r1];
#pragma unroll
    for (int nt = 0; nt < 8; ++nt) {
        int px = nt * 8 + t * 2;
        if (MODE == 0) {
            size_t i0 = ((size_t)b * HIDD + r0) * HWD + y * 64 + px;
            size_t i1 = ((size_t)b * HIDD + r1) * HWD + y * 64 + px;
            *(float2*)(g_t + i0) = make_float2(gelu_exact(acc[nt][0] + b0v),
                                               gelu_exact(acc[nt][1] + b0v));
            *(float2*)(g_t + i1) = make_float2(gelu_exact(acc[nt][2] + b1v),
                                               gelu_exact(acc[nt][3] + b1v));
        } else {
            size_t i0 = ((size_t)b * CC + r0) * HWD + y * 64 + px;
            size_t i1 = ((size_t)b * CC + r1) * HWD + y * 64 + px;
            float2 x0 = *(const float2*)(g_xr + i0);
            float2 x1 = *(const float2*)(g_xr + i1);
            *(float2*)(dout + i0) = make_float2(acc[nt][0] + b0v + x0.x,
                                                acc[nt][1] + b0v + x0.y);
            *(float2*)(dout + i1) = make_float2(acc[nt][2] + b1v + x1.x,
                                                acc[nt][3] + b1v + x1.y);
        }
    }
}

// ---------------------------------------------------------------------------
extern "C" void kernel_launch(void* const* d_in, const int* in_sizes, int n_in,
                              void* d_out, int out_size) {
    (void)in_sizes; (void)n_in; (void)out_size;
    const float* x     = (const float*)d_in[0];
    const float* bn1_g = (const float*)d_in[1];
    const float* bn1_b = (const float*)d_in[2];
    const float* bn1_m = (const float*)d_in[3];
    const float* bn1_v = (const float*)d_in[4];
    const float* kmat  = (const float*)d_in[5];
    const float* vmat  = (const float*)d_in[6];
    const float* bn2_g = (const float*)d_in[7];
    const float* bn2_b = (const float*)d_in[8];
    const float* bn2_m = (const float*)d_in[9];
    const float* bn2_v = (const float*)d_in[10];
    const float* w1    = (const float*)d_in[11];
    const float* b1    = (const float*)d_in[12];
    const float* w2    = (const float*)d_in[13];
    const float* b2    = (const float*)d_in[14];
    float* out = (float*)d_out;

    const int GEMM0_SMEM = (64 * 65 + 2 * 64 * 68) * 4;    // 51456
    const int GEMM1_SMEM = (64 * 65 + 2 * 64 * 132) * 4;   // 84224

    static bool attr_done = false;
    if (!attr_done) {
        cudaFuncSetAttribute(k_gemm_mma<0>, cudaFuncAttributeMaxDynamicSharedMemorySize, GEMM0_SMEM);
        cudaFuncSetAttribute(k_gemm_mma<1>, cudaFuncAttributeMaxDynamicSharedMemorySize, GEMM1_SMEM);
        cudaFuncSetAttribute(k_conv_mma<0>, cudaFuncAttributeMaxDynamicSharedMemorySize, CONV_SMEM);
        cudaFuncSetAttribute(k_conv_mma<1>, cudaFuncAttributeMaxDynamicSharedMemorySize, CONV_SMEM);
        attr_done = true;
    }

    k_fold<<<1, 256>>>(bn1_g, bn1_b, bn1_m, bn1_v, kmat,
                       bn2_g, bn2_b, bn2_m, bn2_v);
    k_prep_w<<<512, 256>>>(w1, w2, vmat);

    dim3 g1(HWD / 64, ICC / 128, BB);
    k_gemm_mma<0><<<g1, 256, GEMM0_SMEM>>>(x);

    k_rowstats<<<BB * ICC, 256>>>();

    dim3 gd(HWD / 256, 8, BB);
    k_dnorm<<<gd, 256>>>();

    dim3 g2(HWD / 64, CC / 128, BB);
    k_gemm_mma<1><<<g2, 256, GEMM1_SMEM>>>(x);

    dim3 gc1(64, HIDD / 128, BB);
    k_conv_mma<0><<<gc1, 256, CONV_SMEM>>>(b1, nullptr);

    dim3 gc2(64, CC / 128, BB);
    k_conv_mma<1><<<gc2, 256, CONV_SMEM>>>(b2, out);
}